// round 13
// baseline (speedup 1.0000x reference)
#include <cuda_runtime.h>
#include <cstdint>

// ---------------------------------------------------------------- dims
#define BATCH 1024
#define HID   512
#define SRC   32
#define TT    32
#define VOC   256
#define EMB   256
#define GIN_K 768
#define G3H   1536
#define NBIG  2048         // Wa(512) + W_hh1(1536)

#define OFF_DEC  0
#define OFF_ATT  (BATCH*TT)
#define OFF_LOSS (OFF_ATT + TT*BATCH*SRC)
#define OFF_COR  (OFF_LOSS + 1)

// ---------------------------------------------------------------- scratch
__device__ float g_kproj[SRC*BATCH*HID];
__device__ float g_Wbig[NBIG*HID];      // [Wa ; W_hh1]
__device__ float g_biasbig[NBIG];
__device__ float g_xrelu[VOC*EMB];      // relu(emb)
__device__ float g_EP[VOC*G3H];         // relu(emb) @ W_ih0[:, :EMB]^T
__device__ float g_h0[BATCH*HID];
__device__ float g_h1[BATCH*HID];
__device__ float g_ctx[BATCH*HID];
__device__ float g_Cbig[BATCH*NBIG];    // [qproj | gh1]
__device__ float g_gi[BATCH*G3H];
__device__ float g_gh[BATCH*G3H];
__device__ float g_logits[BATCH*VOC];
__device__ int   g_tok[BATCH];
__device__ float g_lossacc[BATCH];
__device__ int   g_match[BATCH];

// ---------------------------------------------------------------- 128x64 tile (kproj only; r1-proven + double buffer)
#define BM 128
#define BN 64
#define BK 16
__device__ __forceinline__ void gemm_tile(const float* __restrict__ A, int lda,
                                          const float* __restrict__ W, int ldb,
                                          const float* __restrict__ bias,
                                          float* __restrict__ C, int ldc,
                                          int K, int bm, int bn) {
    __shared__ float As[2][BK][BM];
    __shared__ float Bs[2][BK][BN];
    const int tid = threadIdx.x;
    const int lr = tid >> 2;
    const int lc = (tid & 3) << 2;
    const int crow = (tid >> 4) << 3;
    const int ccol = (tid & 15) << 2;

    float acc[8][4];
#pragma unroll
    for (int i = 0; i < 8; ++i)
#pragma unroll
        for (int j = 0; j < 4; ++j) acc[i][j] = 0.f;

    const int nk = K / BK;
    {
        float4 a0 = *(const float4*)&A[(size_t)(bm + lr) * lda + lc];
        float4 a1 = *(const float4*)&A[(size_t)(bm + lr + 64) * lda + lc];
        float4 b0 = *(const float4*)&W[(size_t)(bn + lr) * ldb + lc];
        As[0][lc+0][lr] = a0.x; As[0][lc+1][lr] = a0.y; As[0][lc+2][lr] = a0.z; As[0][lc+3][lr] = a0.w;
        As[0][lc+0][lr+64] = a1.x; As[0][lc+1][lr+64] = a1.y; As[0][lc+2][lr+64] = a1.z; As[0][lc+3][lr+64] = a1.w;
        Bs[0][lc+0][lr] = b0.x; Bs[0][lc+1][lr] = b0.y; Bs[0][lc+2][lr] = b0.z; Bs[0][lc+3][lr] = b0.w;
    }
    __syncthreads();

    for (int kc = 0; kc < nk; ++kc) {
        const int cur = kc & 1;
        float4 na0, na1, nb0;
        const bool more = (kc + 1 < nk);
        if (more) {
            const int k0 = (kc + 1) * BK;
            na0 = *(const float4*)&A[(size_t)(bm + lr) * lda + k0 + lc];
            na1 = *(const float4*)&A[(size_t)(bm + lr + 64) * lda + k0 + lc];
            nb0 = *(const float4*)&W[(size_t)(bn + lr) * ldb + k0 + lc];
        }
#pragma unroll
        for (int kk = 0; kk < BK; ++kk) {
            float4 bv = *(const float4*)&Bs[cur][kk][ccol];
            float4 av0 = *(const float4*)&As[cur][kk][crow];
            float4 av1 = *(const float4*)&As[cur][kk][crow + 4];
            float a[8] = {av0.x, av0.y, av0.z, av0.w, av1.x, av1.y, av1.z, av1.w};
            float b[4] = {bv.x, bv.y, bv.z, bv.w};
#pragma unroll
            for (int i = 0; i < 8; ++i)
#pragma unroll
                for (int j = 0; j < 4; ++j) acc[i][j] += a[i] * b[j];
        }
        if (more) {
            const int nxt = 1 - cur;
            As[nxt][lc+0][lr] = na0.x; As[nxt][lc+1][lr] = na0.y; As[nxt][lc+2][lr] = na0.z; As[nxt][lc+3][lr] = na0.w;
            As[nxt][lc+0][lr+64] = na1.x; As[nxt][lc+1][lr+64] = na1.y; As[nxt][lc+2][lr+64] = na1.z; As[nxt][lc+3][lr+64] = na1.w;
            Bs[nxt][lc+0][lr] = nb0.x; Bs[nxt][lc+1][lr] = nb0.y; Bs[nxt][lc+2][lr] = nb0.z; Bs[nxt][lc+3][lr] = nb0.w;
        }
        __syncthreads();
    }

    float4 bv = *(const float4*)&bias[bn + ccol];
#pragma unroll
    for (int i = 0; i < 8; ++i) {
        const int row = bm + crow + i;
        float4 r;
        r.x = acc[i][0] + bv.x; r.y = acc[i][1] + bv.y;
        r.z = acc[i][2] + bv.z; r.w = acc[i][3] + bv.w;
        *(float4*)&C[(size_t)row * ldc + bn + ccol] = r;
    }
}

// ---------------------------------------------------------------- 64x64 tile, 128 threads, double-buffered
// Same K-order per output element as gemm_tile -> bit-identical numerics.
#define TB 64
__device__ __forceinline__ void gemm_tile64(const float* __restrict__ A, int lda,
                                            const float* __restrict__ W, int ldb,
                                            const float* __restrict__ bias,
                                            const float* __restrict__ ep,
                                            const int* __restrict__ tok, int ldep,
                                            float* __restrict__ C, int ldc,
                                            int K, int bm, int bn) {
    __shared__ float As[2][BK][TB];
    __shared__ float Bs[2][BK][TB];
    const int tid = threadIdx.x;          // 0..127
    const int lr = tid >> 1;              // 0..63
    const int lc = (tid & 1) << 3;        // 0 or 8
    const int crow = (tid >> 4) << 3;     // 0..56
    const int ccol = (tid & 15) << 2;     // 0..60

    float acc[8][4];
#pragma unroll
    for (int i = 0; i < 8; ++i)
#pragma unroll
        for (int j = 0; j < 4; ++j) acc[i][j] = 0.f;

    const int nk = K / BK;
    {
        float4 a0 = *(const float4*)&A[(size_t)(bm + lr) * lda + lc];
        float4 a1 = *(const float4*)&A[(size_t)(bm + lr) * lda + lc + 4];
        float4 b0 = *(const float4*)&W[(size_t)(bn + lr) * ldb + lc];
        float4 b1 = *(const float4*)&W[(size_t)(bn + lr) * ldb + lc + 4];
        As[0][lc+0][lr] = a0.x; As[0][lc+1][lr] = a0.y; As[0][lc+2][lr] = a0.z; As[0][lc+3][lr] = a0.w;
        As[0][lc+4][lr] = a1.x; As[0][lc+5][lr] = a1.y; As[0][lc+6][lr] = a1.z; As[0][lc+7][lr] = a1.w;
        Bs[0][lc+0][lr] = b0.x; Bs[0][lc+1][lr] = b0.y; Bs[0][lc+2][lr] = b0.z; Bs[0][lc+3][lr] = b0.w;
        Bs[0][lc+4][lr] = b1.x; Bs[0][lc+5][lr] = b1.y; Bs[0][lc+6][lr] = b1.z; Bs[0][lc+7][lr] = b1.w;
    }
    __syncthreads();

    for (int kc = 0; kc < nk; ++kc) {
        const int cur = kc & 1;
        float4 na0, na1, nb0, nb1;
        const bool more = (kc + 1 < nk);
        if (more) {
            const int k0 = (kc + 1) * BK;
            na0 = *(const float4*)&A[(size_t)(bm + lr) * lda + k0 + lc];
            na1 = *(const float4*)&A[(size_t)(bm + lr) * lda + k0 + lc + 4];
            nb0 = *(const float4*)&W[(size_t)(bn + lr) * ldb + k0 + lc];
            nb1 = *(const float4*)&W[(size_t)(bn + lr) * ldb + k0 + lc + 4];
        }
#pragma unroll
        for (int kk = 0; kk < BK; ++kk) {
            float4 bv = *(const float4*)&Bs[cur][kk][ccol];
            float4 av0 = *(const float4*)&As[cur][kk][crow];
            float4 av1 = *(const float4*)&As[cur][kk][crow + 4];
            float a[8] = {av0.x, av0.y, av0.z, av0.w, av1.x, av1.y, av1.z, av1.w};
            float b[4] = {bv.x, bv.y, bv.z, bv.w};
#pragma unroll
            for (int i = 0; i < 8; ++i)
#pragma unroll
                for (int j = 0; j < 4; ++j) acc[i][j] += a[i] * b[j];
        }
        if (more) {
            const int nxt = 1 - cur;
            As[nxt][lc+0][lr] = na0.x; As[nxt][lc+1][lr] = na0.y; As[nxt][lc+2][lr] = na0.z; As[nxt][lc+3][lr] = na0.w;
            As[nxt][lc+4][lr] = na1.x; As[nxt][lc+5][lr] = na1.y; As[nxt][lc+6][lr] = na1.z; As[nxt][lc+7][lr] = na1.w;
            Bs[nxt][lc+0][lr] = nb0.x; Bs[nxt][lc+1][lr] = nb0.y; Bs[nxt][lc+2][lr] = nb0.z; Bs[nxt][lc+3][lr] = nb0.w;
            Bs[nxt][lc+4][lr] = nb1.x; Bs[nxt][lc+5][lr] = nb1.y; Bs[nxt][lc+6][lr] = nb1.z; Bs[nxt][lc+7][lr] = nb1.w;
        }
        __syncthreads();
    }

    float4 bv = bias ? *(const float4*)&bias[bn + ccol] : make_float4(0.f, 0.f, 0.f, 0.f);
#pragma unroll
    for (int i = 0; i < 8; ++i) {
        const int row = bm + crow + i;
        float4 r;
        r.x = acc[i][0] + bv.x; r.y = acc[i][1] + bv.y;
        r.z = acc[i][2] + bv.z; r.w = acc[i][3] + bv.w;
        if (ep) {
            const float4 ev = *(const float4*)&ep[(size_t)tok[row] * ldep + bn + ccol];
            r.x += ev.x; r.y += ev.y; r.z += ev.z; r.w += ev.w;
        }
        *(float4*)&C[(size_t)row * ldc + bn + ccol] = r;
    }
}

// ---------------------------------------------------------------- GEMM wrappers
__global__ void __launch_bounds__(256) k_kproj(const float* __restrict__ enc,
                                               const float* __restrict__ Ua,
                                               const float* __restrict__ bUa) {
    gemm_tile(enc, HID, Ua, HID, bUa, g_kproj, HID, HID,
              blockIdx.y * BM, blockIdx.x * BN);
}

// EP = xrelu @ W_ih0[:, :EMB]^T  (M=256, N=1536, K=256)
__global__ void __launch_bounds__(128) k_ep(const float* __restrict__ W_ih0,
                                            const float* __restrict__ zero) {
    gemm_tile64(g_xrelu, EMB, W_ih0, GIN_K, zero, nullptr, nullptr, 0,
                g_EP, G3H, EMB, blockIdx.y * TB, blockIdx.x * TB);
}

// z=0: Cbig = h1 @ Wbig^T + biasbig  (N=2048)
// z=1: gh   = h0 @ Whh0^T + b_hh0    (N=1536)
__global__ void __launch_bounds__(128) k_dual(const float* __restrict__ Whh0,
                                              const float* __restrict__ b_hh0) {
    if (blockIdx.z == 0) {
        gemm_tile64(g_h1, HID, g_Wbig, HID, g_biasbig, nullptr, nullptr, 0,
                    g_Cbig, NBIG, HID, blockIdx.y * TB, blockIdx.x * TB);
    } else {
        if (blockIdx.x >= G3H / TB) return;
        gemm_tile64(g_h0, HID, Whh0, HID, b_hh0, nullptr, nullptr, 0,
                    g_gh, G3H, HID, blockIdx.y * TB, blockIdx.x * TB);
    }
}

// gi = ctx @ W_ih0[:, EMB:]^T + b_ih0 + EP[tok]   (N=1536, K=512)
__global__ void __launch_bounds__(128) k_gi0(const float* __restrict__ W_ih0,
                                             const float* __restrict__ b_ih0) {
    gemm_tile64(g_ctx, HID, W_ih0 + EMB, GIN_K, b_ih0, g_EP, g_tok, G3H,
                g_gi, G3H, HID, blockIdx.y * TB, blockIdx.x * TB);
}

// gi = h0' @ W_ih1^T + b_ih1   (N=1536, K=512)
__global__ void __launch_bounds__(128) k_gi1(const float* __restrict__ W_ih1,
                                             const float* __restrict__ b_ih1) {
    gemm_tile64(g_h0, HID, W_ih1, HID, b_ih1, nullptr, nullptr, 0,
                g_gi, G3H, HID, blockIdx.y * TB, blockIdx.x * TB);
}

// ---------------------------------------------------------------- logits GEMM: 64x32 tile (proven r12)
#define LBM 64
#define LBN 32
__global__ void __launch_bounds__(128) k_logits(const float* __restrict__ fcW,
                                                const float* __restrict__ fcb) {
    __shared__ float As[BK][LBM];
    __shared__ float Bs[BK][LBN];
    const int tid = threadIdx.x;
    const int bm = blockIdx.y * LBM;
    const int bn = blockIdx.x * LBN;

    const int lrA = tid >> 1;
    const int lcA = (tid & 1) << 3;
    const int lrB = tid >> 2;
    const int lcB = (tid & 3) << 2;
    const int crow = (tid >> 3) << 2;
    const int ccol = (tid & 7) << 2;

    float acc[4][4];
#pragma unroll
    for (int i = 0; i < 4; ++i)
#pragma unroll
        for (int j = 0; j < 4; ++j) acc[i][j] = 0.f;

    for (int k0 = 0; k0 < HID; k0 += BK) {
        float4 a0 = *(const float4*)&g_h1[(size_t)(bm + lrA) * HID + k0 + lcA];
        float4 a1 = *(const float4*)&g_h1[(size_t)(bm + lrA) * HID + k0 + lcA + 4];
        float4 b0 = *(const float4*)&fcW[(size_t)(bn + lrB) * HID + k0 + lcB];
        As[lcA+0][lrA] = a0.x; As[lcA+1][lrA] = a0.y; As[lcA+2][lrA] = a0.z; As[lcA+3][lrA] = a0.w;
        As[lcA+4][lrA] = a1.x; As[lcA+5][lrA] = a1.y; As[lcA+6][lrA] = a1.z; As[lcA+7][lrA] = a1.w;
        Bs[lcB+0][lrB] = b0.x; Bs[lcB+1][lrB] = b0.y; Bs[lcB+2][lrB] = b0.z; Bs[lcB+3][lrB] = b0.w;
        __syncthreads();
#pragma unroll
        for (int kk = 0; kk < BK; ++kk) {
            float4 av = *(const float4*)&As[kk][crow];
            float4 bv = *(const float4*)&Bs[kk][ccol];
            float a[4] = {av.x, av.y, av.z, av.w};
            float b[4] = {bv.x, bv.y, bv.z, bv.w};
#pragma unroll
            for (int i = 0; i < 4; ++i)
#pragma unroll
                for (int j = 0; j < 4; ++j) acc[i][j] += a[i] * b[j];
        }
        __syncthreads();
    }

    const float4 bv = *(const float4*)&fcb[bn + ccol];
#pragma unroll
    for (int i = 0; i < 4; ++i) {
        float4 r;
        r.x = acc[i][0] + bv.x; r.y = acc[i][1] + bv.y;
        r.z = acc[i][2] + bv.z; r.w = acc[i][3] + bv.w;
        *(float4*)&g_logits[(size_t)(bm + crow + i) * VOC + bn + ccol] = r;
    }
}

// ---------------------------------------------------------------- aux kernels
__device__ float g_zero[TB];   // zero bias for k_ep

__global__ void wcat_kernel(const float* __restrict__ Wa, const float* __restrict__ Whh1,
                            const float* __restrict__ bWa, const float* __restrict__ bhh1,
                            const float* __restrict__ emb) {
    int i = blockIdx.x * blockDim.x + threadIdx.x;   // NBIG*HID
    int row = i >> 9, col = i & 511;
    g_Wbig[i] = (row < HID) ? Wa[row * HID + col] : Whh1[(row - HID) * HID + col];
    if (i < HID) g_biasbig[i] = bWa[i];
    else if (i < NBIG) g_biasbig[i] = bhh1[i - HID];
    if (i < VOC * EMB) {
        float v = emb[i];
        g_xrelu[i] = v > 0.f ? v : 0.f;
    }
    if (i < TB) g_zero[i] = 0.f;
}

__global__ void init_kernel(const float* __restrict__ state) {
    int idx = blockIdx.x * blockDim.x + threadIdx.x;
    if (idx < BATCH * HID) {
        g_h0[idx] = state[idx];
        g_h1[idx] = state[BATCH * HID + idx];
    }
    if (idx < BATCH) { g_tok[idx] = 1; g_lossacc[idx] = 0.f; g_match[idx] = 1; }
}

__global__ void __launch_bounds__(256) attn_kernel(const float* __restrict__ enc,
                                                   const float* __restrict__ Va,
                                                   const float* __restrict__ bVa,
                                                   float* __restrict__ out_attn, int t) {
    int b = blockIdx.x;
    int warp = threadIdx.x >> 5, lane = threadIdx.x & 31;
    __shared__ float e_sh[SRC];
    __shared__ float w_sh[SRC];

    float part[4] = {0.f, 0.f, 0.f, 0.f};
    for (int h = lane; h < HID; h += 32) {
        float q = g_Cbig[(size_t)b * NBIG + h];
        float va = Va[h];
#pragma unroll
        for (int i = 0; i < 4; ++i) {
            int s = warp * 4 + i;
            part[i] += va * tanhf(q + g_kproj[((size_t)s * BATCH + b) * HID + h]);
        }
    }
#pragma unroll
    for (int i = 0; i < 4; ++i) {
#pragma unroll
        for (int o = 16; o > 0; o >>= 1) part[i] += __shfl_xor_sync(0xffffffffu, part[i], o);
        if (lane == 0) e_sh[warp * 4 + i] = part[i] + bVa[0];
    }
    __syncthreads();
    if (threadIdx.x < 32) {
        float x = e_sh[lane], m = x;
#pragma unroll
        for (int o = 16; o > 0; o >>= 1) m = fmaxf(m, __shfl_xor_sync(0xffffffffu, m, o));
        float ex = expf(x - m), s = ex;
#pragma unroll
        for (int o = 16; o > 0; o >>= 1) s += __shfl_xor_sync(0xffffffffu, s, o);
        float w = ex / s;
        w_sh[lane] = w;
        out_attn[((size_t)t * BATCH + b) * SRC + lane] = w;
    }
    __syncthreads();
    for (int h = threadIdx.x; h < HID; h += 256) {
        float c = 0.f;
#pragma unroll
        for (int s = 0; s < SRC; ++s) c += w_sh[s] * enc[((size_t)s * BATCH + b) * HID + h];
        g_ctx[b * HID + h] = c;
    }
}

__device__ __forceinline__ float sigmf(float x) { return 1.f / (1.f + expf(-x)); }

__global__ void gru_pw0() {
    int idx = blockIdx.x * blockDim.x + threadIdx.x;
    int b = idx >> 9, j = idx & 511;
    const float* gib = g_gi + (size_t)b * G3H;
    const float* ghb = g_gh + (size_t)b * G3H;
    float r = sigmf(gib[j] + ghb[j]);
    float z = sigmf(gib[HID + j] + ghb[HID + j]);
    float n = tanhf(gib[2 * HID + j] + r * ghb[2 * HID + j]);
    float hp = g_h0[idx];
    g_h0[idx] = (1.f - z) * n + z * hp;
}

__global__ void gru_pw1() {
    int idx = blockIdx.x * blockDim.x + threadIdx.x;
    int b = idx >> 9, j = idx & 511;
    const float* gib = g_gi + (size_t)b * G3H;
    const float* ghb = g_Cbig + (size_t)b * NBIG + HID;
    float r = sigmf(gib[j] + ghb[j]);
    float z = sigmf(gib[HID + j] + ghb[HID + j]);
    float n = tanhf(gib[2 * HID + j] + r * ghb[2 * HID + j]);
    float hp = g_h1[idx];
    g_h1[idx] = (1.f - z) * n + z * hp;
}

__global__ void __launch_bounds__(256) fc_finalize(const int* __restrict__ target,
                                                   float* __restrict__ out_dec, int t) {
    int b = blockIdx.x;
    int v = threadIdx.x;
    float lg = g_logits[b * VOC + v];
    __shared__ float sval[VOC];
    __shared__ int sidx[VOC];
    sval[v] = lg; sidx[v] = v;
    __syncthreads();
    for (int off = 128; off > 0; off >>= 1) {
        if (v < off) {
            float ov = sval[v + off]; int oi = sidx[v + off];
            if (ov > sval[v] || (ov == sval[v] && oi < sidx[v])) { sval[v] = ov; sidx[v] = oi; }
        }
        __syncthreads();
    }
    float m = sval[0]; int am = sidx[0];
    __syncthreads();
    sval[v] = expf(lg - m);
    __syncthreads();
    for (int off = 128; off > 0; off >>= 1) {
        if (v < off) sval[v] += sval[v + off];
        __syncthreads();
    }
    if (v == 0) {
        float lse = m + logf(sval[0]);
        int tgt = target[b * TT + t];
        g_lossacc[b] += lse - g_logits[b * VOC + tgt];
        if (am != tgt) g_match[b] = 0;
        g_tok[b] = am;
        out_dec[b * TT + t] = (float)am;
    }
}

__global__ void __launch_bounds__(256) final_reduce(float* __restrict__ out) {
    __shared__ float sl[256];
    __shared__ int sc[256];
    float l = 0.f; int c = 0;
    for (int b = threadIdx.x; b < BATCH; b += 256) { l += g_lossacc[b]; c += g_match[b]; }
    sl[threadIdx.x] = l; sc[threadIdx.x] = c;
    __syncthreads();
    for (int off = 128; off > 0; off >>= 1) {
        if (threadIdx.x < off) { sl[threadIdx.x] += sl[threadIdx.x + off]; sc[threadIdx.x] += sc[threadIdx.x + off]; }
        __syncthreads();
    }
    if (threadIdx.x == 0) {
        out[OFF_LOSS] = sl[0] / (float)BATCH;
        out[OFF_COR] = (float)sc[0];
    }
}

// ---------------------------------------------------------------- launch
extern "C" void kernel_launch(void* const* d_in, const int* in_sizes, int n_in,
                              void* d_out, int out_size) {
    const float* state = (const float*)d_in[0];
    const float* enc   = (const float*)d_in[1];
    const int*   tgt   = (const int*)d_in[2];
    const float* emb   = (const float*)d_in[3];
    const float* Wa    = (const float*)d_in[4];
    const float* bWa   = (const float*)d_in[5];
    const float* Ua    = (const float*)d_in[6];
    const float* bUa   = (const float*)d_in[7];
    const float* Va    = (const float*)d_in[8];
    const float* bVa   = (const float*)d_in[9];
    const float* W_ih0 = (const float*)d_in[10];
    const float* W_hh0 = (const float*)d_in[11];
    const float* b_ih0 = (const float*)d_in[12];
    const float* b_hh0 = (const float*)d_in[13];
    const float* W_ih1 = (const float*)d_in[14];
    const float* W_hh1 = (const float*)d_in[15];
    const float* b_ih1 = (const float*)d_in[16];
    const float* b_hh1 = (const float*)d_in[17];
    const float* fcW   = (const float*)d_in[18];
    const float* fcb   = (const float*)d_in[19];
    float* out = (float*)d_out;

    float* p_zero;
    cudaGetSymbolAddress((void**)&p_zero, g_zero);

    // ---- init + weight prep ----
    init_kernel<<<(BATCH * HID + 255) / 256, 256>>>(state);
    wcat_kernel<<<(NBIG * HID + 255) / 256, 256>>>(Wa, W_hh1, bWa, b_hh1, emb);

    // kproj = enc @ Ua^T + bUa   (M=32768, N=512): 2048 big tiles
    k_kproj<<<dim3(HID / BN, (SRC * BATCH) / BM), 256>>>(enc, Ua, bUa);
    // EP = relu(emb) @ W_ih0[:, :EMB]^T   (M=256, N=1536): 96 small tiles
    k_ep<<<dim3(G3H / TB, VOC / TB), 128>>>(W_ih0, p_zero);

    for (int t = 0; t < TT; ++t) {
        // step start: [qproj|gh1] = h1@Wbig (32x16) + gh0 = h0@Whh0 (24x16)
        k_dual<<<dim3(NBIG / TB, BATCH / TB, 2), 128>>>(W_hh0, b_hh0);
        attn_kernel<<<BATCH, 256>>>(enc, Va, bVa, out + OFF_ATT, t);
        // gi0 (24x16 small tiles)
        k_gi0<<<dim3(G3H / TB, BATCH / TB), 128>>>(W_ih0, b_ih0);
        gru_pw0<<<(BATCH * HID) / 256, 256>>>();
        // gi1 (24x16 small tiles)
        k_gi1<<<dim3(G3H / TB, BATCH / TB), 128>>>(W_ih1, b_ih1);
        gru_pw1<<<(BATCH * HID) / 256, 256>>>();
        // logits (64x32 tiles, 128 blocks)
        k_logits<<<dim3(VOC / LBN, BATCH / LBM), 128>>>(fcW, fcb);
        fc_finalize<<<BATCH, 256>>>(tgt, out + OFF_DEC, t);
    }

    final_reduce<<<1, 256>>>(out);
}

// round 14
// speedup vs baseline: 1.0436x; 1.0436x over previous
#include <cuda_runtime.h>
#include <cstdint>

// ---------------------------------------------------------------- dims
#define BATCH 1024
#define HID   512
#define SRC   32
#define TT    32
#define VOC   256
#define EMB   256
#define GIN_K 768
#define G3H   1536
#define NBIG  2048         // Wa(512) + W_hh1(1536)
#define KH    256          // K half

#define OFF_DEC  0
#define OFF_ATT  (BATCH*TT)
#define OFF_LOSS (OFF_ATT + TT*BATCH*SRC)
#define OFF_COR  (OFF_LOSS + 1)

// ---------------------------------------------------------------- scratch
__device__ float g_kproj[SRC*BATCH*HID];
__device__ float g_Wbig[NBIG*HID];      // [Wa ; W_hh1]
__device__ float g_biasbig[NBIG];
__device__ float g_xrelu[VOC*EMB];      // relu(emb)
__device__ float g_EP[VOC*G3H];         // relu(emb) @ W_ih0[:, :EMB]^T
__device__ float g_h0[BATCH*HID];
__device__ float g_h1[BATCH*HID];
__device__ float g_ctx[BATCH*HID];
__device__ float g_Cbig[BATCH*NBIG];    // [qproj | gh1]  partial K=0..255
__device__ float g_Cbig2[BATCH*NBIG];   // partial K=256..511
__device__ float g_gi[BATCH*G3H];
__device__ float g_gi2[BATCH*G3H];
__device__ float g_gh[BATCH*G3H];
__device__ float g_gh2[BATCH*G3H];
__device__ float g_logits[BATCH*VOC];
__device__ int   g_tok[BATCH];
__device__ float g_lossacc[BATCH];
__device__ int   g_match[BATCH];

// ---------------------------------------------------------------- 128x64 tile (r12-proven, double-buffered)
#define BM 128
#define BN 64
#define BK 16
__device__ __forceinline__ void gemm_tile(const float* __restrict__ A, int lda,
                                          const float* __restrict__ W, int ldb,
                                          const float* __restrict__ bias,
                                          const float* __restrict__ ep,
                                          const int* __restrict__ tok, int ldep,
                                          float* __restrict__ C, int ldc,
                                          int K, int bm, int bn) {
    __shared__ float As[2][BK][BM];
    __shared__ float Bs[2][BK][BN];
    const int tid = threadIdx.x;
    const int lr = tid >> 2;
    const int lc = (tid & 3) << 2;
    const int crow = (tid >> 4) << 3;
    const int ccol = (tid & 15) << 2;

    float acc[8][4];
#pragma unroll
    for (int i = 0; i < 8; ++i)
#pragma unroll
        for (int j = 0; j < 4; ++j) acc[i][j] = 0.f;

    const int nk = K / BK;
    {
        float4 a0 = *(const float4*)&A[(size_t)(bm + lr) * lda + lc];
        float4 a1 = *(const float4*)&A[(size_t)(bm + lr + 64) * lda + lc];
        float4 b0 = *(const float4*)&W[(size_t)(bn + lr) * ldb + lc];
        As[0][lc+0][lr] = a0.x; As[0][lc+1][lr] = a0.y; As[0][lc+2][lr] = a0.z; As[0][lc+3][lr] = a0.w;
        As[0][lc+0][lr+64] = a1.x; As[0][lc+1][lr+64] = a1.y; As[0][lc+2][lr+64] = a1.z; As[0][lc+3][lr+64] = a1.w;
        Bs[0][lc+0][lr] = b0.x; Bs[0][lc+1][lr] = b0.y; Bs[0][lc+2][lr] = b0.z; Bs[0][lc+3][lr] = b0.w;
    }
    __syncthreads();

    for (int kc = 0; kc < nk; ++kc) {
        const int cur = kc & 1;
        float4 na0, na1, nb0;
        const bool more = (kc + 1 < nk);
        if (more) {
            const int k0 = (kc + 1) * BK;
            na0 = *(const float4*)&A[(size_t)(bm + lr) * lda + k0 + lc];
            na1 = *(const float4*)&A[(size_t)(bm + lr + 64) * lda + k0 + lc];
            nb0 = *(const float4*)&W[(size_t)(bn + lr) * ldb + k0 + lc];
        }
#pragma unroll
        for (int kk = 0; kk < BK; ++kk) {
            float4 bv = *(const float4*)&Bs[cur][kk][ccol];
            float4 av0 = *(const float4*)&As[cur][kk][crow];
            float4 av1 = *(const float4*)&As[cur][kk][crow + 4];
            float a[8] = {av0.x, av0.y, av0.z, av0.w, av1.x, av1.y, av1.z, av1.w};
            float b[4] = {bv.x, bv.y, bv.z, bv.w};
#pragma unroll
            for (int i = 0; i < 8; ++i)
#pragma unroll
                for (int j = 0; j < 4; ++j) acc[i][j] += a[i] * b[j];
        }
        if (more) {
            const int nxt = 1 - cur;
            As[nxt][lc+0][lr] = na0.x; As[nxt][lc+1][lr] = na0.y; As[nxt][lc+2][lr] = na0.z; As[nxt][lc+3][lr] = na0.w;
            As[nxt][lc+0][lr+64] = na1.x; As[nxt][lc+1][lr+64] = na1.y; As[nxt][lc+2][lr+64] = na1.z; As[nxt][lc+3][lr+64] = na1.w;
            Bs[nxt][lc+0][lr] = nb0.x; Bs[nxt][lc+1][lr] = nb0.y; Bs[nxt][lc+2][lr] = nb0.z; Bs[nxt][lc+3][lr] = nb0.w;
        }
        __syncthreads();
    }

    float4 bv = bias ? *(const float4*)&bias[bn + ccol] : make_float4(0.f, 0.f, 0.f, 0.f);
#pragma unroll
    for (int i = 0; i < 8; ++i) {
        const int row = bm + crow + i;
        float4 r;
        r.x = acc[i][0] + bv.x; r.y = acc[i][1] + bv.y;
        r.z = acc[i][2] + bv.z; r.w = acc[i][3] + bv.w;
        if (ep) {
            const float4 ev = *(const float4*)&ep[(size_t)tok[row] * ldep + bn + ccol];
            r.x += ev.x; r.y += ev.y; r.z += ev.z; r.w += ev.w;
        }
        *(float4*)&C[(size_t)row * ldc + bn + ccol] = r;
    }
}

// ---------------------------------------------------------------- GEMM wrappers
__global__ void __launch_bounds__(256) k_kproj(const float* __restrict__ enc,
                                               const float* __restrict__ Ua,
                                               const float* __restrict__ bUa) {
    gemm_tile(enc, HID, Ua, HID, bUa, nullptr, nullptr, 0,
              g_kproj, HID, HID, blockIdx.y * BM, blockIdx.x * BN);
}

// EP = xrelu @ W_ih0[:, :EMB]^T  (M=256, N=1536, K=256)
__global__ void __launch_bounds__(256) k_ep(const float* __restrict__ W_ih0) {
    gemm_tile(g_xrelu, EMB, W_ih0, GIN_K, nullptr, nullptr, nullptr, 0,
              g_EP, G3H, EMB, blockIdx.y * BM, blockIdx.x * BN);
}

// z = (khalf<<1) | which:  which 0 -> Cbig partial, which 1 -> gh partial
__global__ void __launch_bounds__(256) k_dual(const float* __restrict__ Whh0,
                                              const float* __restrict__ b_hh0) {
    const int which = blockIdx.z & 1;
    const int kh = blockIdx.z >> 1;
    const int koff = kh * KH;
    if (which == 0) {
        gemm_tile(g_h1 + koff, HID, g_Wbig + koff, HID,
                  kh == 0 ? g_biasbig : nullptr, nullptr, nullptr, 0,
                  kh == 0 ? g_Cbig : g_Cbig2, NBIG, KH,
                  blockIdx.y * BM, blockIdx.x * BN);
    } else {
        if (blockIdx.x >= G3H / BN) return;
        gemm_tile(g_h0 + koff, HID, Whh0 + koff, HID,
                  kh == 0 ? b_hh0 : nullptr, nullptr, nullptr, 0,
                  kh == 0 ? g_gh : g_gh2, G3H, KH,
                  blockIdx.y * BM, blockIdx.x * BN);
    }
}

// gi partials: ctx @ W_ih0[:, EMB+koff:]^T (+ b_ih0 + EP[tok] on kh0)
__global__ void __launch_bounds__(256) k_gi0(const float* __restrict__ W_ih0,
                                             const float* __restrict__ b_ih0) {
    const int kh = blockIdx.z;
    const int koff = kh * KH;
    gemm_tile(g_ctx + koff, HID, W_ih0 + EMB + koff, GIN_K,
              kh == 0 ? b_ih0 : nullptr,
              kh == 0 ? g_EP : nullptr, g_tok, G3H,
              kh == 0 ? g_gi : g_gi2, G3H, KH,
              blockIdx.y * BM, blockIdx.x * BN);
}

// gi partials: h0' @ W_ih1^T (+ b_ih1 on kh0)
__global__ void __launch_bounds__(256) k_gi1(const float* __restrict__ W_ih1,
                                             const float* __restrict__ b_ih1) {
    const int kh = blockIdx.z;
    const int koff = kh * KH;
    gemm_tile(g_h0 + koff, HID, W_ih1 + koff, HID,
              kh == 0 ? b_ih1 : nullptr, nullptr, nullptr, 0,
              kh == 0 ? g_gi : g_gi2, G3H, KH,
              blockIdx.y * BM, blockIdx.x * BN);
}

// ---------------------------------------------------------------- logits GEMM: 64x32 tile (proven r12)
#define LBM 64
#define LBN 32
__global__ void __launch_bounds__(128) k_logits(const float* __restrict__ fcW,
                                                const float* __restrict__ fcb) {
    __shared__ float As[BK][LBM];
    __shared__ float Bs[BK][LBN];
    const int tid = threadIdx.x;
    const int bm = blockIdx.y * LBM;
    const int bn = blockIdx.x * LBN;

    const int lrA = tid >> 1;
    const int lcA = (tid & 1) << 3;
    const int lrB = tid >> 2;
    const int lcB = (tid & 3) << 2;
    const int crow = (tid >> 3) << 2;
    const int ccol = (tid & 7) << 2;

    float acc[4][4];
#pragma unroll
    for (int i = 0; i < 4; ++i)
#pragma unroll
        for (int j = 0; j < 4; ++j) acc[i][j] = 0.f;

    for (int k0 = 0; k0 < HID; k0 += BK) {
        float4 a0 = *(const float4*)&g_h1[(size_t)(bm + lrA) * HID + k0 + lcA];
        float4 a1 = *(const float4*)&g_h1[(size_t)(bm + lrA) * HID + k0 + lcA + 4];
        float4 b0 = *(const float4*)&fcW[(size_t)(bn + lrB) * HID + k0 + lcB];
        As[lcA+0][lrA] = a0.x; As[lcA+1][lrA] = a0.y; As[lcA+2][lrA] = a0.z; As[lcA+3][lrA] = a0.w;
        As[lcA+4][lrA] = a1.x; As[lcA+5][lrA] = a1.y; As[lcA+6][lrA] = a1.z; As[lcA+7][lrA] = a1.w;
        Bs[lcB+0][lrB] = b0.x; Bs[lcB+1][lrB] = b0.y; Bs[lcB+2][lrB] = b0.z; Bs[lcB+3][lrB] = b0.w;
        __syncthreads();
#pragma unroll
        for (int kk = 0; kk < BK; ++kk) {
            float4 av = *(const float4*)&As[kk][crow];
            float4 bv = *(const float4*)&Bs[kk][ccol];
            float a[4] = {av.x, av.y, av.z, av.w};
            float b[4] = {bv.x, bv.y, bv.z, bv.w};
#pragma unroll
            for (int i = 0; i < 4; ++i)
#pragma unroll
                for (int j = 0; j < 4; ++j) acc[i][j] += a[i] * b[j];
        }
        __syncthreads();
    }

    const float4 bv = *(const float4*)&fcb[bn + ccol];
#pragma unroll
    for (int i = 0; i < 4; ++i) {
        float4 r;
        r.x = acc[i][0] + bv.x; r.y = acc[i][1] + bv.y;
        r.z = acc[i][2] + bv.z; r.w = acc[i][3] + bv.w;
        *(float4*)&g_logits[(size_t)(bm + crow + i) * VOC + bn + ccol] = r;
    }
}

// ---------------------------------------------------------------- aux kernels
__global__ void wcat_kernel(const float* __restrict__ Wa, const float* __restrict__ Whh1,
                            const float* __restrict__ bWa, const float* __restrict__ bhh1,
                            const float* __restrict__ emb) {
    int i = blockIdx.x * blockDim.x + threadIdx.x;
    int row = i >> 9, col = i & 511;
    g_Wbig[i] = (row < HID) ? Wa[row * HID + col] : Whh1[(row - HID) * HID + col];
    if (i < HID) g_biasbig[i] = bWa[i];
    else if (i < NBIG) g_biasbig[i] = bhh1[i - HID];
    if (i < VOC * EMB) {
        float v = emb[i];
        g_xrelu[i] = v > 0.f ? v : 0.f;
    }
}

__global__ void init_kernel(const float* __restrict__ state) {
    int idx = blockIdx.x * blockDim.x + threadIdx.x;
    if (idx < BATCH * HID) {
        g_h0[idx] = state[idx];
        g_h1[idx] = state[BATCH * HID + idx];
    }
    if (idx < BATCH) { g_tok[idx] = 1; g_lossacc[idx] = 0.f; g_match[idx] = 1; }
}

__global__ void __launch_bounds__(256) attn_kernel(const float* __restrict__ enc,
                                                   const float* __restrict__ Va,
                                                   const float* __restrict__ bVa,
                                                   float* __restrict__ out_attn, int t) {
    int b = blockIdx.x;
    int warp = threadIdx.x >> 5, lane = threadIdx.x & 31;
    __shared__ float e_sh[SRC];
    __shared__ float w_sh[SRC];

    float part[4] = {0.f, 0.f, 0.f, 0.f};
    for (int h = lane; h < HID; h += 32) {
        float q = g_Cbig[(size_t)b * NBIG + h] + g_Cbig2[(size_t)b * NBIG + h];
        float va = Va[h];
#pragma unroll
        for (int i = 0; i < 4; ++i) {
            int s = warp * 4 + i;
            part[i] += va * tanhf(q + g_kproj[((size_t)s * BATCH + b) * HID + h]);
        }
    }
#pragma unroll
    for (int i = 0; i < 4; ++i) {
#pragma unroll
        for (int o = 16; o > 0; o >>= 1) part[i] += __shfl_xor_sync(0xffffffffu, part[i], o);
        if (lane == 0) e_sh[warp * 4 + i] = part[i] + bVa[0];
    }
    __syncthreads();
    if (threadIdx.x < 32) {
        float x = e_sh[lane], m = x;
#pragma unroll
        for (int o = 16; o > 0; o >>= 1) m = fmaxf(m, __shfl_xor_sync(0xffffffffu, m, o));
        float ex = expf(x - m), s = ex;
#pragma unroll
        for (int o = 16; o > 0; o >>= 1) s += __shfl_xor_sync(0xffffffffu, s, o);
        float w = ex / s;
        w_sh[lane] = w;
        out_attn[((size_t)t * BATCH + b) * SRC + lane] = w;
    }
    __syncthreads();
    for (int h = threadIdx.x; h < HID; h += 256) {
        float c = 0.f;
#pragma unroll
        for (int s = 0; s < SRC; ++s) c += w_sh[s] * enc[((size_t)s * BATCH + b) * HID + h];
        g_ctx[b * HID + h] = c;
    }
}

__device__ __forceinline__ float sigmf(float x) { return 1.f / (1.f + expf(-x)); }

__global__ void gru_pw0() {
    int idx = blockIdx.x * blockDim.x + threadIdx.x;
    int b = idx >> 9, j = idx & 511;
    const size_t o = (size_t)b * G3H;
    float gr = g_gi[o + j] + g_gi2[o + j];
    float gz = g_gi[o + HID + j] + g_gi2[o + HID + j];
    float gn = g_gi[o + 2 * HID + j] + g_gi2[o + 2 * HID + j];
    float hr = g_gh[o + j] + g_gh2[o + j];
    float hz = g_gh[o + HID + j] + g_gh2[o + HID + j];
    float hn = g_gh[o + 2 * HID + j] + g_gh2[o + 2 * HID + j];
    float r = sigmf(gr + hr);
    float z = sigmf(gz + hz);
    float n = tanhf(gn + r * hn);
    float hp = g_h0[idx];
    g_h0[idx] = (1.f - z) * n + z * hp;
}

__global__ void gru_pw1() {
    int idx = blockIdx.x * blockDim.x + threadIdx.x;
    int b = idx >> 9, j = idx & 511;
    const size_t o = (size_t)b * G3H;
    const size_t oc = (size_t)b * NBIG + HID;
    float gr = g_gi[o + j] + g_gi2[o + j];
    float gz = g_gi[o + HID + j] + g_gi2[o + HID + j];
    float gn = g_gi[o + 2 * HID + j] + g_gi2[o + 2 * HID + j];
    float hr = g_Cbig[oc + j] + g_Cbig2[oc + j];
    float hz = g_Cbig[oc + HID + j] + g_Cbig2[oc + HID + j];
    float hn = g_Cbig[oc + 2 * HID + j] + g_Cbig2[oc + 2 * HID + j];
    float r = sigmf(gr + hr);
    float z = sigmf(gz + hz);
    float n = tanhf(gn + r * hn);
    float hp = g_h1[idx];
    g_h1[idx] = (1.f - z) * n + z * hp;
}

__global__ void __launch_bounds__(256) fc_finalize(const int* __restrict__ target,
                                                   float* __restrict__ out_dec, int t) {
    int b = blockIdx.x;
    int v = threadIdx.x;
    float lg = g_logits[b * VOC + v];
    __shared__ float sval[VOC];
    __shared__ int sidx[VOC];
    sval[v] = lg; sidx[v] = v;
    __syncthreads();
    for (int off = 128; off > 0; off >>= 1) {
        if (v < off) {
            float ov = sval[v + off]; int oi = sidx[v + off];
            if (ov > sval[v] || (ov == sval[v] && oi < sidx[v])) { sval[v] = ov; sidx[v] = oi; }
        }
        __syncthreads();
    }
    float m = sval[0]; int am = sidx[0];
    __syncthreads();
    sval[v] = expf(lg - m);
    __syncthreads();
    for (int off = 128; off > 0; off >>= 1) {
        if (v < off) sval[v] += sval[v + off];
        __syncthreads();
    }
    if (v == 0) {
        float lse = m + logf(sval[0]);
        int tgt = target[b * TT + t];
        g_lossacc[b] += lse - g_logits[b * VOC + tgt];
        if (am != tgt) g_match[b] = 0;
        g_tok[b] = am;
        out_dec[b * TT + t] = (float)am;
    }
}

__global__ void __launch_bounds__(256) final_reduce(float* __restrict__ out) {
    __shared__ float sl[256];
    __shared__ int sc[256];
    float l = 0.f; int c = 0;
    for (int b = threadIdx.x; b < BATCH; b += 256) { l += g_lossacc[b]; c += g_match[b]; }
    sl[threadIdx.x] = l; sc[threadIdx.x] = c;
    __syncthreads();
    for (int off = 128; off > 0; off >>= 1) {
        if (threadIdx.x < off) { sl[threadIdx.x] += sl[threadIdx.x + off]; sc[threadIdx.x] += sc[threadIdx.x + off]; }
        __syncthreads();
    }
    if (threadIdx.x == 0) {
        out[OFF_LOSS] = sl[0] / (float)BATCH;
        out[OFF_COR] = (float)sc[0];
    }
}

// ---------------------------------------------------------------- launch
extern "C" void kernel_launch(void* const* d_in, const int* in_sizes, int n_in,
                              void* d_out, int out_size) {
    const float* state = (const float*)d_in[0];
    const float* enc   = (const float*)d_in[1];
    const int*   tgt   = (const int*)d_in[2];
    const float* emb   = (const float*)d_in[3];
    const float* Wa    = (const float*)d_in[4];
    const float* bWa   = (const float*)d_in[5];
    const float* Ua    = (const float*)d_in[6];
    const float* bUa   = (const float*)d_in[7];
    const float* Va    = (const float*)d_in[8];
    const float* bVa   = (const float*)d_in[9];
    const float* W_ih0 = (const float*)d_in[10];
    const float* W_hh0 = (const float*)d_in[11];
    const float* b_ih0 = (const float*)d_in[12];
    const float* b_hh0 = (const float*)d_in[13];
    const float* W_ih1 = (const float*)d_in[14];
    const float* W_hh1 = (const float*)d_in[15];
    const float* b_ih1 = (const float*)d_in[16];
    const float* b_hh1 = (const float*)d_in[17];
    const float* fcW   = (const float*)d_in[18];
    const float* fcb   = (const float*)d_in[19];
    float* out = (float*)d_out;

    // ---- init + weight prep ----
    init_kernel<<<(BATCH * HID + 255) / 256, 256>>>(state);
    wcat_kernel<<<(NBIG * HID + 255) / 256, 256>>>(Wa, W_hh1, bWa, b_hh1, emb);

    // kproj = enc @ Ua^T + bUa   (M=32768, N=512)
    k_kproj<<<dim3(HID / BN, (SRC * BATCH) / BM), 256>>>(enc, Ua, bUa);
    // EP = relu(emb) @ W_ih0[:, :EMB]^T   (M=256, N=1536)
    k_ep<<<dim3(G3H / BN, VOC / BM), 256>>>(W_ih0);

    for (int t = 0; t < TT; ++t) {
        // K-split dual: z = (kh<<1)|which -> 4 planes, 896 blocks total
        k_dual<<<dim3(NBIG / BN, BATCH / BM, 4), 256>>>(W_hh0, b_hh0);
        attn_kernel<<<BATCH, 256>>>(enc, Va, bVa, out + OFF_ATT, t);
        // gi0 partials (z = kh), 384 blocks
        k_gi0<<<dim3(G3H / BN, BATCH / BM, 2), 256>>>(W_ih0, b_ih0);
        gru_pw0<<<(BATCH * HID) / 256, 256>>>();
        // gi1 partials (z = kh), 384 blocks
        k_gi1<<<dim3(G3H / BN, BATCH / BM, 2), 256>>>(W_ih1, b_ih1);
        gru_pw1<<<(BATCH * HID) / 256, 256>>>();
        // logits
        k_logits<<<dim3(VOC / LBN, BATCH / LBM), 128>>>(fcW, fcb);
        fc_finalize<<<BATCH, 256>>>(tgt, out + OFF_DEC, t);
    }

    final_reduce<<<1, 256>>>(out);
}